// round 1
// baseline (speedup 1.0000x reference)
#include <cuda_runtime.h>
#include <math.h>

// Full attention, fp32 SIMT flash-attention baseline.
// B=2, N=2048, H=16, D=64. out[b,q,h,d] = softmax(QK^T/sqrt(D)) V
//
// Layout: q,k,v,out all [B, N, H, D] (row stride between tokens = H*D = 1024 floats).

namespace {

constexpr int B = 2;
constexpr int N = 2048;
constexpr int H = 16;
constexpr int D = 64;

constexpr int BQ = 128;      // query rows per block
constexpr int BK = 64;       // key/value rows per tile
constexpr int THREADS = 256; // ty in [0,32) x tx in [0,8)
constexpr int PS = D + 1;    // padded row stride (65) for all smem tiles

// smem: Qs[BQ][PS] + Ks[BK][PS] + Vs[BK][PS] + Ps[BQ][PS]
constexpr int SMEM_FLOATS = BQ * PS + BK * PS + BK * PS + BQ * PS;
constexpr int SMEM_BYTES = SMEM_FLOATS * (int)sizeof(float);

__global__ __launch_bounds__(THREADS, 2)
void fa_fp32_kernel(const float* __restrict__ q,
                    const float* __restrict__ k,
                    const float* __restrict__ v,
                    float* __restrict__ out)
{
    extern __shared__ float sm[];
    float* Qs = sm;                 // [BQ][PS]
    float* Ks = Qs + BQ * PS;       // [BK][PS]
    float* Vs = Ks + BK * PS;       // [BK][PS]
    float* Ps = Vs + BK * PS;       // [BQ][PS]

    const int tid = threadIdx.x;
    const int tx = tid & 7;         // column-group lane (8)
    const int ty = tid >> 3;        // row group (32) -> 4 rows each

    const int q0 = blockIdx.x * BQ;
    const int bh = blockIdx.y;
    const int b = bh / H;
    const int h = bh % H;

    const float scale = 0.125f;     // 1/sqrt(64)

    const size_t rowstride = (size_t)H * D;  // 1024
    const float* qbase = q + (size_t)b * N * rowstride + (size_t)h * D;
    const float* kbase = k + (size_t)b * N * rowstride + (size_t)h * D;
    const float* vbase = v + (size_t)b * N * rowstride + (size_t)h * D;
    float* obase = out + (size_t)b * N * rowstride + (size_t)h * D;

    // ---- Load Q tile (pre-scaled by 1/sqrt(D)) ----
    // 128 rows x 64 floats = 2048 float4; 8 per thread.
    // 16 consecutive threads cover one row (coalesced 256B).
    #pragma unroll
    for (int i = 0; i < (BQ * D) / (THREADS * 4); i++) {
        int idx = tid + i * THREADS;
        int row = idx >> 4;
        int d4 = (idx & 15) << 2;
        float4 val = *reinterpret_cast<const float4*>(
            qbase + (size_t)(q0 + row) * rowstride + d4);
        float* dst = Qs + row * PS + d4;
        dst[0] = val.x * scale;
        dst[1] = val.y * scale;
        dst[2] = val.z * scale;
        dst[3] = val.w * scale;
    }

    // ---- Accumulators ----
    float o[4][8];
    float m_i[4], l_i[4];
    #pragma unroll
    for (int r = 0; r < 4; r++) {
        m_i[r] = -INFINITY;
        l_i[r] = 0.0f;
        #pragma unroll
        for (int c = 0; c < 8; c++) o[r][c] = 0.0f;
    }

    for (int k0 = 0; k0 < N; k0 += BK) {
        __syncthreads();  // prev GEMM2 done with Ks/Vs/Ps

        // ---- Load K and V tiles ----
        #pragma unroll
        for (int i = 0; i < (BK * D) / (THREADS * 4); i++) {
            int idx = tid + i * THREADS;
            int row = idx >> 4;
            int d4 = (idx & 15) << 2;
            size_t goff = (size_t)(k0 + row) * rowstride + d4;
            float4 kv = *reinterpret_cast<const float4*>(kbase + goff);
            float* kd = Ks + row * PS + d4;
            kd[0] = kv.x; kd[1] = kv.y; kd[2] = kv.z; kd[3] = kv.w;
            float4 vv = *reinterpret_cast<const float4*>(vbase + goff);
            float* vd = Vs + row * PS + d4;
            vd[0] = vv.x; vd[1] = vv.y; vd[2] = vv.z; vd[3] = vv.w;
        }
        __syncthreads();

        // ---- GEMM1: S = (Q*scale) @ K^T ----
        // Thread owns rows ty*4+r, cols c*8+tx (stride-1 across lanes: conflict-free).
        float s[4][8];
        #pragma unroll
        for (int r = 0; r < 4; r++)
            #pragma unroll
            for (int c = 0; c < 8; c++) s[r][c] = 0.0f;

        #pragma unroll 8
        for (int d = 0; d < D; d++) {
            float qv[4], kv[8];
            #pragma unroll
            for (int r = 0; r < 4; r++) qv[r] = Qs[(ty * 4 + r) * PS + d];
            #pragma unroll
            for (int c = 0; c < 8; c++) kv[c] = Ks[(c * 8 + tx) * PS + d];
            #pragma unroll
            for (int r = 0; r < 4; r++)
                #pragma unroll
                for (int c = 0; c < 8; c++)
                    s[r][c] = fmaf(qv[r], kv[c], s[r][c]);
        }

        // ---- Online softmax (rows owned by ty; reduce across 8 tx lanes) ----
        #pragma unroll
        for (int r = 0; r < 4; r++) {
            float mt = s[r][0];
            #pragma unroll
            for (int c = 1; c < 8; c++) mt = fmaxf(mt, s[r][c]);
            mt = fmaxf(mt, __shfl_xor_sync(0xffffffffu, mt, 1, 8));
            mt = fmaxf(mt, __shfl_xor_sync(0xffffffffu, mt, 2, 8));
            mt = fmaxf(mt, __shfl_xor_sync(0xffffffffu, mt, 4, 8));

            float mnew = fmaxf(m_i[r], mt);
            float alpha = __expf(m_i[r] - mnew);
            m_i[r] = mnew;

            float ls = 0.0f;
            #pragma unroll
            for (int c = 0; c < 8; c++) {
                float p = __expf(s[r][c] - mnew);
                s[r][c] = p;
                ls += p;
            }
            ls += __shfl_xor_sync(0xffffffffu, ls, 1, 8);
            ls += __shfl_xor_sync(0xffffffffu, ls, 2, 8);
            ls += __shfl_xor_sync(0xffffffffu, ls, 4, 8);

            l_i[r] = l_i[r] * alpha + ls;
            #pragma unroll
            for (int c = 0; c < 8; c++) o[r][c] *= alpha;

            float* prow = Ps + (ty * 4 + r) * PS;
            #pragma unroll
            for (int c = 0; c < 8; c++) prow[c * 8 + tx] = s[r][c];
        }
        __syncthreads();  // Ps visible to all

        // ---- GEMM2: O += P @ V ----
        #pragma unroll 8
        for (int j = 0; j < BK; j++) {
            float pv[4], vv[8];
            #pragma unroll
            for (int r = 0; r < 4; r++) pv[r] = Ps[(ty * 4 + r) * PS + j];
            #pragma unroll
            for (int c = 0; c < 8; c++) vv[c] = Vs[j * PS + c * 8 + tx];
            #pragma unroll
            for (int r = 0; r < 4; r++)
                #pragma unroll
                for (int c = 0; c < 8; c++)
                    o[r][c] = fmaf(pv[r], vv[c], o[r][c]);
        }
    }

    // ---- Epilogue: normalize and store ----
    #pragma unroll
    for (int r = 0; r < 4; r++) {
        float inv = 1.0f / l_i[r];
        float* orow = obase + (size_t)(q0 + ty * 4 + r) * rowstride;
        #pragma unroll
        for (int c = 0; c < 8; c++) {
            orow[c * 8 + tx] = o[r][c] * inv;
        }
    }
}

}  // namespace

extern "C" void kernel_launch(void* const* d_in, const int* in_sizes, int n_in,
                              void* d_out, int out_size)
{
    const float* q = (const float*)d_in[0];
    const float* k = (const float*)d_in[1];
    const float* v = (const float*)d_in[2];
    float* out = (float*)d_out;

    cudaFuncSetAttribute(fa_fp32_kernel,
                         cudaFuncAttributeMaxDynamicSharedMemorySize, SMEM_BYTES);

    dim3 grid(N / BQ, B * H);
    fa_fp32_kernel<<<grid, THREADS, SMEM_BYTES>>>(q, k, v, out);
}

// round 4
// speedup vs baseline: 2.8485x; 2.8485x over previous
#include <cuda_runtime.h>
#include <cuda_bf16.h>
#include <stdint.h>
#include <math.h>

// Flash attention via mma.sync bf16 3x-split (compute_103-safe: no tcgen05).
// B=2, N=2048, H=16, D=64, fp32 in/out. out = softmax(QK^T/8) V.

#define SW128(o) ((o) ^ (((o) >> 3) & 0x70))

namespace {

constexpr int N = 2048;
constexpr int BQ = 128;
constexpr int BK = 128;
constexpr int THREADS = 256;
constexpr int NT = N / BK;  // 16

// smem byte offsets: Qhi, Qlo, then double-buffered Khi/Klo/Vhi/Vlo (16KB each).
// Buffer stride 64KB between buf 0 and buf 1.
constexpr uint32_t OQH = 0, OQL = 16384;
constexpr uint32_t OKH0 = 32768;
constexpr uint32_t OKL0 = 49152;
constexpr uint32_t OVH0 = 65536;
constexpr uint32_t OVL0 = 81920;
constexpr uint32_t BUFSTRIDE = 65536;
constexpr uint32_t SMEM_BYTES = 163840;

__device__ __forceinline__ uint32_t okh(int buf) { return OKH0 + (uint32_t)buf * BUFSTRIDE; }
__device__ __forceinline__ uint32_t okl(int buf) { return OKL0 + (uint32_t)buf * BUFSTRIDE; }
__device__ __forceinline__ uint32_t ovh(int buf) { return OVH0 + (uint32_t)buf * BUFSTRIDE; }
__device__ __forceinline__ uint32_t ovl(int buf) { return OVL0 + (uint32_t)buf * BUFSTRIDE; }

__device__ __forceinline__ uint32_t smem_u32(const void* p) {
    uint32_t a;
    asm("{ .reg .u64 t; cvta.to.shared.u64 t, %1; cvt.u32.u64 %0, t; }" : "=r"(a) : "l"(p));
    return a;
}

// pack (x0 -> low bf16, x1 -> high bf16)
__device__ __forceinline__ uint32_t pk(float x0, float x1) {
    uint32_t r;
    asm("cvt.rn.bf16x2.f32 %0, %2, %1;" : "=r"(r) : "f"(x0), "f"(x1));
    return r;
}

// split (x0,x1) into hi bf16x2 + lo bf16x2 residuals
__device__ __forceinline__ void split2(float x0, float x1, uint32_t& h, uint32_t& l) {
    h = pk(x0, x1);
    float h0 = __uint_as_float(h << 16);
    float h1 = __uint_as_float(h & 0xffff0000u);
    l = pk(x0 - h0, x1 - h1);
}

__device__ __forceinline__ float ex2(float x) {
    float r; asm("ex2.approx.f32 %0, %1;" : "=f"(r) : "f"(x)); return r;
}

__device__ __forceinline__ void ldsm4(uint32_t a, uint32_t& r0, uint32_t& r1,
                                      uint32_t& r2, uint32_t& r3) {
    asm volatile("ldmatrix.sync.aligned.m8n8.x4.shared.b16 {%0,%1,%2,%3}, [%4];"
                 : "=r"(r0), "=r"(r1), "=r"(r2), "=r"(r3) : "r"(a));
}

__device__ __forceinline__ void ldsm4t(uint32_t a, uint32_t& r0, uint32_t& r1,
                                       uint32_t& r2, uint32_t& r3) {
    asm volatile("ldmatrix.sync.aligned.m8n8.x4.trans.shared.b16 {%0,%1,%2,%3}, [%4];"
                 : "=r"(r0), "=r"(r1), "=r"(r2), "=r"(r3) : "r"(a));
}

__device__ __forceinline__ void mma16816(float* c, const uint32_t* a, uint32_t b0, uint32_t b1) {
    asm volatile("mma.sync.aligned.m16n8k16.row.col.f32.bf16.bf16.f32 "
                 "{%0,%1,%2,%3}, {%4,%5,%6,%7}, {%8,%9}, {%0,%1,%2,%3};"
                 : "+f"(c[0]), "+f"(c[1]), "+f"(c[2]), "+f"(c[3])
                 : "r"(a[0]), "r"(a[1]), "r"(a[2]), "r"(a[3]), "r"(b0), "r"(b1));
}

// ---- global<->smem staging (fp32 -> bf16 hi/lo SW128 tiles) ----

__device__ __forceinline__ void ldg_tile(const float* __restrict__ gb, int r0,
                                         int tid, float4* w) {
    #pragma unroll
    for (int i = 0; i < 8; i++) {
        int idx = tid + i * THREADS;
        int r = idx >> 4, c4 = (idx & 15) << 2;
        w[i] = *reinterpret_cast<const float4*>(gb + (size_t)(r0 + r) * 1024 + c4);
    }
}

__device__ __forceinline__ void sts_tile(char* sm, uint32_t oh, uint32_t ol,
                                         int tid, const float4* w) {
    #pragma unroll
    for (int i = 0; i < 8; i++) {
        int idx = tid + i * THREADS;
        int r = idx >> 4, c4 = (idx & 15) << 2;
        uint32_t h0, l0_, h1, l1_;
        split2(w[i].x, w[i].y, h0, l0_);
        split2(w[i].z, w[i].w, h1, l1_);
        uint32_t off = SW128((uint32_t)(r * 128 + c4 * 2));
        *reinterpret_cast<uint2*>(sm + oh + off) = make_uint2(h0, h1);
        *reinterpret_cast<uint2*>(sm + ol + off) = make_uint2(l0_, l1_);
    }
}

__global__ __launch_bounds__(THREADS, 1)
void fa_mma_kernel(const float* __restrict__ q, const float* __restrict__ k,
                   const float* __restrict__ v, float* __restrict__ out)
{
    extern __shared__ char sm[];
    const uint32_t smb = smem_u32(sm);
    const int tid = threadIdx.x;
    const int lane = tid & 31;
    const int wid = tid >> 5;
    const int g = lane >> 2;       // accumulator row within 8
    const int u = lane & 3;        // accumulator col pair
    const int li = lane & 7;       // ldmatrix row lane
    const int sel = lane >> 3;     // ldmatrix matrix select

    const int q0 = blockIdx.x * BQ;
    const int bh = blockIdx.y;
    const int b = bh >> 4;
    const int h = bh & 15;

    const size_t rs = 1024;  // token stride (H*D)
    const float* qb = q + (size_t)b * N * rs + (size_t)h * 64;
    const float* kb = k + (size_t)b * N * rs + (size_t)h * 64;
    const float* vb = v + (size_t)b * N * rs + (size_t)h * 64;
    float* ob = out + (size_t)b * N * rs + (size_t)h * 64;

    const float QSCALE = 0.125f * 1.44269504088896340736f;  // 1/sqrt(64) * log2(e)

    // ---- prologue: stage Q (scaled), K0, V0 ----
    {
        #pragma unroll
        for (int i = 0; i < 8; i++) {
            int idx = tid + i * THREADS;
            int r = idx >> 4, c4 = (idx & 15) << 2;
            float4 w = *reinterpret_cast<const float4*>(qb + (size_t)(q0 + r) * rs + c4);
            uint32_t h0, l0_, h1, l1_;
            split2(w.x * QSCALE, w.y * QSCALE, h0, l0_);
            split2(w.z * QSCALE, w.w * QSCALE, h1, l1_);
            uint32_t off = SW128((uint32_t)(r * 128 + c4 * 2));
            *reinterpret_cast<uint2*>(sm + OQH + off) = make_uint2(h0, h1);
            *reinterpret_cast<uint2*>(sm + OQL + off) = make_uint2(l0_, l1_);
        }
        float4 w0[8], w1[8];
        ldg_tile(kb, 0, tid, w0);
        ldg_tile(vb, 0, tid, w1);
        sts_tile(sm, okh(0), okl(0), tid, w0);
        sts_tile(sm, ovh(0), ovl(0), tid, w1);
    }
    __syncthreads();

    // ---- Q fragments (persist in registers) ----
    uint32_t qh[4][4], ql[4][4];
    {
        int qrow = wid * 16 + li + ((sel & 1) ? 8 : 0);
        #pragma unroll
        for (int ks = 0; ks < 4; ks++) {
            uint32_t off = (uint32_t)(qrow * 128 + ks * 32 + ((sel & 2) ? 16 : 0));
            ldsm4(smb + OQH + SW128(off), qh[ks][0], qh[ks][1], qh[ks][2], qh[ks][3]);
            ldsm4(smb + OQL + SW128(off), ql[ks][0], ql[ks][1], ql[ks][2], ql[ks][3]);
        }
    }

    float mrow0 = -INFINITY, mrow1 = -INFINITY;
    float lsum0 = 0.0f, lsum1 = 0.0f;
    float o[8][4];
    #pragma unroll
    for (int n = 0; n < 8; n++)
        #pragma unroll
        for (int j = 0; j < 4; j++) o[n][j] = 0.0f;

    for (int t = 0; t < NT; t++) {
        const int cur = t & 1;
        const int nxt = cur ^ 1;
        const bool pf = (t + 1 < NT);
        __syncthreads();

        // prefetch K(t+1) into regs
        float4 kreg[8];
        if (pf) ldg_tile(kb, (t + 1) * BK, tid, kreg);

        // ---- GEMM1: S(16x128) = Q K^T, 3x bf16 split ----
        float s[16][4];
        #pragma unroll
        for (int n = 0; n < 16; n++)
            #pragma unroll
            for (int j = 0; j < 4; j++) s[n][j] = 0.0f;

        const uint32_t kbh = smb + okh(cur), kbl = smb + okl(cur);
        #pragma unroll
        for (int nt = 0; nt < 16; nt++) {
            uint32_t bhv[4][2], blv[4][2];
            uint32_t base = (uint32_t)((nt * 8 + li) * 128 + sel * 16);
            ldsm4(kbh + SW128(base),      bhv[0][0], bhv[0][1], bhv[1][0], bhv[1][1]);
            ldsm4(kbh + SW128(base + 64), bhv[2][0], bhv[2][1], bhv[3][0], bhv[3][1]);
            ldsm4(kbl + SW128(base),      blv[0][0], blv[0][1], blv[1][0], blv[1][1]);
            ldsm4(kbl + SW128(base + 64), blv[2][0], blv[2][1], blv[3][0], blv[3][1]);
            #pragma unroll
            for (int ks = 0; ks < 4; ks++) {
                mma16816(s[nt], qh[ks], bhv[ks][0], bhv[ks][1]);
                mma16816(s[nt], qh[ks], blv[ks][0], blv[ks][1]);
                mma16816(s[nt], ql[ks], bhv[ks][0], bhv[ks][1]);
            }
        }

        // drain K prefetch; start V prefetch
        if (pf) sts_tile(sm, okh(nxt), okl(nxt), tid, kreg);
        float4 vreg[8];
        if (pf) ldg_tile(vb, (t + 1) * BK, tid, vreg);

        // ---- online softmax (warp-local rows; exp2 domain) ----
        float tm0 = s[0][0], tm1 = s[0][2];
        #pragma unroll
        for (int nt = 0; nt < 16; nt++) {
            tm0 = fmaxf(tm0, fmaxf(s[nt][0], s[nt][1]));
            tm1 = fmaxf(tm1, fmaxf(s[nt][2], s[nt][3]));
        }
        tm0 = fmaxf(tm0, __shfl_xor_sync(0xffffffffu, tm0, 1));
        tm0 = fmaxf(tm0, __shfl_xor_sync(0xffffffffu, tm0, 2));
        tm1 = fmaxf(tm1, __shfl_xor_sync(0xffffffffu, tm1, 1));
        tm1 = fmaxf(tm1, __shfl_xor_sync(0xffffffffu, tm1, 2));

        float mn0 = fmaxf(mrow0, tm0), mn1 = fmaxf(mrow1, tm1);
        float a0 = ex2(mrow0 - mn0), a1 = ex2(mrow1 - mn1);
        mrow0 = mn0; mrow1 = mn1;
        lsum0 *= a0; lsum1 *= a1;

        #pragma unroll
        for (int nt = 0; nt < 16; nt++) {
            s[nt][0] = ex2(s[nt][0] - mn0);
            s[nt][1] = ex2(s[nt][1] - mn0);
            s[nt][2] = ex2(s[nt][2] - mn1);
            s[nt][3] = ex2(s[nt][3] - mn1);
            lsum0 += s[nt][0] + s[nt][1];
            lsum1 += s[nt][2] + s[nt][3];
        }
        #pragma unroll
        for (int n = 0; n < 8; n++) {
            o[n][0] *= a0; o[n][1] *= a0;
            o[n][2] *= a1; o[n][3] *= a1;
        }

        // drain V prefetch
        if (pf) sts_tile(sm, ovh(nxt), ovl(nxt), tid, vreg);

        // ---- GEMM2: O(16x64) += P V, 3x bf16 split; P from registers ----
        const uint32_t vbh = smb + ovh(cur), vbl = smb + ovl(cur);
        #pragma unroll
        for (int ks = 0; ks < 8; ks++) {
            uint32_t ah[4], al[4];
            split2(s[2 * ks][0],     s[2 * ks][1],     ah[0], al[0]);
            split2(s[2 * ks][2],     s[2 * ks][3],     ah[1], al[1]);
            split2(s[2 * ks + 1][0], s[2 * ks + 1][1], ah[2], al[2]);
            split2(s[2 * ks + 1][2], s[2 * ks + 1][3], ah[3], al[3]);
            uint32_t vbase = (uint32_t)((ks * 16 + li + ((sel & 1) ? 8 : 0)) * 128
                                        + ((sel & 2) ? 16 : 0));
            #pragma unroll
            for (int pr = 0; pr < 4; pr++) {
                uint32_t r0, r1, r2, r3, t0, t1, t2, t3;
                uint32_t off = vbase + pr * 32;
                ldsm4t(vbh + SW128(off), r0, r1, r2, r3);
                ldsm4t(vbl + SW128(off), t0, t1, t2, t3);
                mma16816(o[2 * pr],     ah, r0, r1);
                mma16816(o[2 * pr],     ah, t0, t1);
                mma16816(o[2 * pr],     al, r0, r1);
                mma16816(o[2 * pr + 1], ah, r2, r3);
                mma16816(o[2 * pr + 1], ah, t2, t3);
                mma16816(o[2 * pr + 1], al, r2, r3);
            }
        }
    }

    // ---- epilogue ----
    lsum0 += __shfl_xor_sync(0xffffffffu, lsum0, 1);
    lsum0 += __shfl_xor_sync(0xffffffffu, lsum0, 2);
    lsum1 += __shfl_xor_sync(0xffffffffu, lsum1, 1);
    lsum1 += __shfl_xor_sync(0xffffffffu, lsum1, 2);
    float i0 = 1.0f / lsum0, i1 = 1.0f / lsum1;

    const int row0 = q0 + wid * 16 + g;
    #pragma unroll
    for (int nt = 0; nt < 8; nt++) {
        *reinterpret_cast<float2*>(ob + (size_t)row0 * rs + nt * 8 + 2 * u) =
            make_float2(o[nt][0] * i0, o[nt][1] * i0);
        *reinterpret_cast<float2*>(ob + (size_t)(row0 + 8) * rs + nt * 8 + 2 * u) =
            make_float2(o[nt][2] * i1, o[nt][3] * i1);
    }
}

}  // namespace

extern "C" void kernel_launch(void* const* d_in, const int* in_sizes, int n_in,
                              void* d_out, int out_size)
{
    (void)in_sizes; (void)n_in; (void)out_size;
    const float* q = (const float*)d_in[0];
    const float* k = (const float*)d_in[1];
    const float* v = (const float*)d_in[2];
    float* out = (float*)d_out;

    cudaFuncSetAttribute(fa_mma_kernel,
                         cudaFuncAttributeMaxDynamicSharedMemorySize, SMEM_BYTES);

    dim3 grid(N / BQ, 2 * 16);
    fa_mma_kernel<<<grid, THREADS, SMEM_BYTES>>>(q, k, v, out);
}

// round 5
// speedup vs baseline: 2.9996x; 1.0530x over previous
#include <cuda_runtime.h>
#include <cuda_bf16.h>
#include <stdint.h>
#include <math.h>

// Flash attention, mma.sync bf16 3x-split + bf16 pre-pass + cp.async pipeline.
// B=2, N=2048, H=16, D=64, fp32 in/out. out = softmax(QK^T/8) V.

#define SW128(o) ((o) ^ (((o) >> 3) & 0x70))

namespace {

constexpr int N = 2048;
constexpr int BQ = 128;
constexpr int BK = 64;
constexpr int THREADS = 256;
constexpr int NT = N / BK;  // 32

constexpr float QSCALE = 0.125f * 1.44269504088896340736f;  // 1/sqrt(64)*log2(e)

// bf16 scratch planes: [qhi,qlo,khi,klo,vhi,vlo], each [32 bh][2048 n][64 d]
constexpr size_t PL = (size_t)32 * 2048 * 64;
__device__ __nv_bfloat16 g_scr[6 * PL];

// smem layout (bytes): Qhi 16K, Qlo 16K, then 2 KV buffers of 32K each
// (KH 8K, KL 8K, VH 8K, VL 8K).
constexpr uint32_t OQH = 0, OQL = 16384;
constexpr uint32_t OKV0 = 32768;
constexpr uint32_t KVSTRIDE = 32768;
constexpr uint32_t SUB_KH = 0, SUB_KL = 8192, SUB_VH = 16384, SUB_VL = 24576;
constexpr uint32_t SMEM_BYTES = 98304;  // 96KB -> 2 CTAs/SM

__device__ __forceinline__ uint32_t smem_u32(const void* p) {
    uint32_t a;
    asm("{ .reg .u64 t; cvta.to.shared.u64 t, %1; cvt.u32.u64 %0, t; }" : "=r"(a) : "l"(p));
    return a;
}

__device__ __forceinline__ uint32_t pk(float x0, float x1) {
    uint32_t r;
    asm("cvt.rn.bf16x2.f32 %0, %2, %1;" : "=r"(r) : "f"(x0), "f"(x1));
    return r;
}

__device__ __forceinline__ void split2(float x0, float x1, uint32_t& h, uint32_t& l) {
    h = pk(x0, x1);
    float h0 = __uint_as_float(h << 16);
    float h1 = __uint_as_float(h & 0xffff0000u);
    l = pk(x0 - h0, x1 - h1);
}

__device__ __forceinline__ float ex2(float x) {
    float r; asm("ex2.approx.f32 %0, %1;" : "=f"(r) : "f"(x)); return r;
}

__device__ __forceinline__ void ldsm4(uint32_t a, uint32_t& r0, uint32_t& r1,
                                      uint32_t& r2, uint32_t& r3) {
    asm volatile("ldmatrix.sync.aligned.m8n8.x4.shared.b16 {%0,%1,%2,%3}, [%4];"
                 : "=r"(r0), "=r"(r1), "=r"(r2), "=r"(r3) : "r"(a));
}

__device__ __forceinline__ void ldsm4t(uint32_t a, uint32_t& r0, uint32_t& r1,
                                       uint32_t& r2, uint32_t& r3) {
    asm volatile("ldmatrix.sync.aligned.m8n8.x4.trans.shared.b16 {%0,%1,%2,%3}, [%4];"
                 : "=r"(r0), "=r"(r1), "=r"(r2), "=r"(r3) : "r"(a));
}

__device__ __forceinline__ void mma16816(float* c, const uint32_t* a, uint32_t b0, uint32_t b1) {
    asm volatile("mma.sync.aligned.m16n8k16.row.col.f32.bf16.bf16.f32 "
                 "{%0,%1,%2,%3}, {%4,%5,%6,%7}, {%8,%9}, {%0,%1,%2,%3};"
                 : "+f"(c[0]), "+f"(c[1]), "+f"(c[2]), "+f"(c[3])
                 : "r"(a[0]), "r"(a[1]), "r"(a[2]), "r"(a[3]), "r"(b0), "r"(b1));
}

__device__ __forceinline__ void cpa16(uint32_t dst, const void* src) {
    asm volatile("cp.async.ca.shared.global [%0], [%1], 16;" :: "r"(dst), "l"(src));
}
__device__ __forceinline__ void cpa_commit() {
    asm volatile("cp.async.commit_group;" ::: "memory");
}
template <int n>
__device__ __forceinline__ void cpa_wait() {
    asm volatile("cp.async.wait_group %0;" :: "n"(n) : "memory");
}

// ---------------- pre-pass: fp32 -> bf16 hi/lo planes, [bh][n][64] ----------------
__global__ void prepass_kernel(const float* __restrict__ q,
                               const float* __restrict__ k,
                               const float* __restrict__ v)
{
    const int which = blockIdx.y;  // 0=q, 1=k, 2=v
    const float* src = (which == 0) ? q : ((which == 1) ? k : v);
    const float scale = (which == 0) ? QSCALE : 1.0f;
    __nv_bfloat16* hi = g_scr + (size_t)(2 * which) * PL;
    __nv_bfloat16* lo = hi + PL;

    size_t i = (size_t)blockIdx.x * blockDim.x + threadIdx.x;  // float4 index
    float4 w = reinterpret_cast<const float4*>(src)[i];
    uint32_t d4 = (uint32_t)(i & 15) << 2;
    uint32_t nh = (uint32_t)(i >> 4);
    uint32_t h = nh & 15;
    uint32_t bn = nh >> 4;       // b*2048 + n
    uint32_t n = bn & 2047;
    uint32_t b = bn >> 11;
    size_t o = ((size_t)(b * 16 + h) * 2048 + n) * 64 + d4;

    uint32_t h0, l0, h1, l1;
    split2(w.x * scale, w.y * scale, h0, l0);
    split2(w.z * scale, w.w * scale, h1, l1);
    *reinterpret_cast<uint2*>(hi + o) = make_uint2(h0, h1);
    *reinterpret_cast<uint2*>(lo + o) = make_uint2(l0, l1);
}

// ---------------- main kernel ----------------
__global__ __launch_bounds__(THREADS, 2)
void fa_mma_kernel(float* __restrict__ out)
{
    extern __shared__ char sm[];
    const uint32_t smb = smem_u32(sm);
    const int tid = threadIdx.x;
    const int lane = tid & 31;
    const int wid = tid >> 5;
    const int g = lane >> 2;
    const int u = lane & 3;
    const int li = lane & 7;
    const int sel = lane >> 3;

    const int q0 = blockIdx.x * BQ;
    const int bh = blockIdx.y;        // b*16 + h
    const int b = bh >> 4;
    const int h = bh & 15;

    const __nv_bfloat16* qhi_p = g_scr + 0 * PL + (size_t)bh * 2048 * 64;
    const __nv_bfloat16* qlo_p = g_scr + 1 * PL + (size_t)bh * 2048 * 64;
    const __nv_bfloat16* khi_p = g_scr + 2 * PL + (size_t)bh * 2048 * 64;
    const __nv_bfloat16* klo_p = g_scr + 3 * PL + (size_t)bh * 2048 * 64;
    const __nv_bfloat16* vhi_p = g_scr + 4 * PL + (size_t)bh * 2048 * 64;
    const __nv_bfloat16* vlo_p = g_scr + 5 * PL + (size_t)bh * 2048 * 64;

    const size_t rs = 1024;
    float* ob = out + (size_t)b * N * rs + (size_t)h * 64;

    // ---- issue Q cp.asyncs (group 1) ----
    #pragma unroll
    for (int j = 0; j < 4; j++) {
        int idx = tid + j * THREADS;       // 0..1023 over 128 rows x 8 chunks
        int row = idx >> 3, c = idx & 7;
        uint32_t off = SW128((uint32_t)(row * 128 + c * 16));
        cpa16(smb + OQH + off, qhi_p + (size_t)(q0 + row) * 64 + c * 8);
        cpa16(smb + OQL + off, qlo_p + (size_t)(q0 + row) * 64 + c * 8);
    }
    cpa_commit();

    // ---- KV tile issuer: 64 rows x 128B per subtile, 2 chunks/thread/subtile ----
    auto issue_kv = [&](int buf, int t) {
        uint32_t base = smb + OKV0 + (uint32_t)buf * KVSTRIDE;
        int k0 = t * BK;
        #pragma unroll
        for (int j = 0; j < 2; j++) {
            int idx = tid + j * THREADS;   // 0..511 over 64 rows x 8 chunks
            int row = idx >> 3, c = idx & 7;
            uint32_t off = SW128((uint32_t)(row * 128 + c * 16));
            size_t go = (size_t)(k0 + row) * 64 + c * 8;
            cpa16(base + SUB_KH + off, khi_p + go);
            cpa16(base + SUB_KL + off, klo_p + go);
            cpa16(base + SUB_VH + off, vhi_p + go);
            cpa16(base + SUB_VL + off, vlo_p + go);
        }
        cpa_commit();
    };

    issue_kv(0, 0);      // group 2
    cpa_wait<1>();       // Q ready
    __syncthreads();

    // ---- Q fragments ----
    uint32_t qh[4][4], ql[4][4];
    {
        int qrow = wid * 16 + li + ((sel & 1) ? 8 : 0);
        #pragma unroll
        for (int ks = 0; ks < 4; ks++) {
            uint32_t off = (uint32_t)(qrow * 128 + ks * 32 + ((sel & 2) ? 16 : 0));
            ldsm4(smb + OQH + SW128(off), qh[ks][0], qh[ks][1], qh[ks][2], qh[ks][3]);
            ldsm4(smb + OQL + SW128(off), ql[ks][0], ql[ks][1], ql[ks][2], ql[ks][3]);
        }
    }

    float mrow0 = -INFINITY, mrow1 = -INFINITY;
    float lsum0 = 0.0f, lsum1 = 0.0f;
    float o[8][4];
    #pragma unroll
    for (int n = 0; n < 8; n++)
        #pragma unroll
        for (int j = 0; j < 4; j++) o[n][j] = 0.0f;

    for (int t = 0; t < NT; t++) {
        const int cur = t & 1;
        const int nxt = cur ^ 1;
        const bool pf = (t + 1 < NT);

        __syncthreads();             // all warps done reading buf[nxt] (tile t-1)
        if (pf) issue_kv(nxt, t + 1);
        if (pf) cpa_wait<1>(); else cpa_wait<0>();
        __syncthreads();             // buf[cur] visible

        const uint32_t kb = smb + OKV0 + (uint32_t)cur * KVSTRIDE;

        // ---- GEMM1: S(16x64) = Q K^T ----
        float s[8][4];
        #pragma unroll
        for (int n = 0; n < 8; n++)
            #pragma unroll
            for (int j = 0; j < 4; j++) s[n][j] = 0.0f;

        #pragma unroll
        for (int nt = 0; nt < 8; nt++) {
            uint32_t bhv[4][2], blv[4][2];
            uint32_t base = (uint32_t)((nt * 8 + li) * 128 + sel * 16);
            ldsm4(kb + SUB_KH + SW128(base),      bhv[0][0], bhv[0][1], bhv[1][0], bhv[1][1]);
            ldsm4(kb + SUB_KH + SW128(base + 64), bhv[2][0], bhv[2][1], bhv[3][0], bhv[3][1]);
            ldsm4(kb + SUB_KL + SW128(base),      blv[0][0], blv[0][1], blv[1][0], blv[1][1]);
            ldsm4(kb + SUB_KL + SW128(base + 64), blv[2][0], blv[2][1], blv[3][0], blv[3][1]);
            #pragma unroll
            for (int ks = 0; ks < 4; ks++) {
                mma16816(s[nt], qh[ks], bhv[ks][0], bhv[ks][1]);
                mma16816(s[nt], qh[ks], blv[ks][0], blv[ks][1]);
                mma16816(s[nt], ql[ks], bhv[ks][0], bhv[ks][1]);
            }
        }

        // ---- online softmax (exp2 domain) ----
        float tm0 = s[0][0], tm1 = s[0][2];
        #pragma unroll
        for (int nt = 0; nt < 8; nt++) {
            tm0 = fmaxf(tm0, fmaxf(s[nt][0], s[nt][1]));
            tm1 = fmaxf(tm1, fmaxf(s[nt][2], s[nt][3]));
        }
        tm0 = fmaxf(tm0, __shfl_xor_sync(0xffffffffu, tm0, 1));
        tm0 = fmaxf(tm0, __shfl_xor_sync(0xffffffffu, tm0, 2));
        tm1 = fmaxf(tm1, __shfl_xor_sync(0xffffffffu, tm1, 1));
        tm1 = fmaxf(tm1, __shfl_xor_sync(0xffffffffu, tm1, 2));

        float mn0 = fmaxf(mrow0, tm0), mn1 = fmaxf(mrow1, tm1);
        float a0 = ex2(mrow0 - mn0), a1 = ex2(mrow1 - mn1);
        mrow0 = mn0; mrow1 = mn1;
        lsum0 *= a0; lsum1 *= a1;

        #pragma unroll
        for (int nt = 0; nt < 8; nt++) {
            s[nt][0] = ex2(s[nt][0] - mn0);
            s[nt][1] = ex2(s[nt][1] - mn0);
            s[nt][2] = ex2(s[nt][2] - mn1);
            s[nt][3] = ex2(s[nt][3] - mn1);
            lsum0 += s[nt][0] + s[nt][1];
            lsum1 += s[nt][2] + s[nt][3];
        }
        #pragma unroll
        for (int n = 0; n < 8; n++) {
            o[n][0] *= a0; o[n][1] *= a0;
            o[n][2] *= a1; o[n][3] *= a1;
        }

        // ---- GEMM2: O(16x64) += P V ----
        #pragma unroll
        for (int ks = 0; ks < 4; ks++) {
            uint32_t ah[4], al[4];
            split2(s[2 * ks][0],     s[2 * ks][1],     ah[0], al[0]);
            split2(s[2 * ks][2],     s[2 * ks][3],     ah[1], al[1]);
            split2(s[2 * ks + 1][0], s[2 * ks + 1][1], ah[2], al[2]);
            split2(s[2 * ks + 1][2], s[2 * ks + 1][3], ah[3], al[3]);
            uint32_t vbase = (uint32_t)((ks * 16 + li + ((sel & 1) ? 8 : 0)) * 128
                                        + ((sel & 2) ? 16 : 0));
            #pragma unroll
            for (int pr = 0; pr < 4; pr++) {
                uint32_t r0, r1, r2, r3, t0, t1, t2, t3;
                uint32_t off = vbase + pr * 32;
                ldsm4t(kb + SUB_VH + SW128(off), r0, r1, r2, r3);
                ldsm4t(kb + SUB_VL + SW128(off), t0, t1, t2, t3);
                mma16816(o[2 * pr],     ah, r0, r1);
                mma16816(o[2 * pr],     ah, t0, t1);
                mma16816(o[2 * pr],     al, r0, r1);
                mma16816(o[2 * pr + 1], ah, r2, r3);
                mma16816(o[2 * pr + 1], ah, t2, t3);
                mma16816(o[2 * pr + 1], al, r2, r3);
            }
        }
    }

    // ---- epilogue ----
    lsum0 += __shfl_xor_sync(0xffffffffu, lsum0, 1);
    lsum0 += __shfl_xor_sync(0xffffffffu, lsum0, 2);
    lsum1 += __shfl_xor_sync(0xffffffffu, lsum1, 1);
    lsum1 += __shfl_xor_sync(0xffffffffu, lsum1, 2);
    float i0 = 1.0f / lsum0, i1 = 1.0f / lsum1;

    const int row0 = q0 + wid * 16 + g;
    #pragma unroll
    for (int nt = 0; nt < 8; nt++) {
        *reinterpret_cast<float2*>(ob + (size_t)row0 * rs + nt * 8 + 2 * u) =
            make_float2(o[nt][0] * i0, o[nt][1] * i0);
        *reinterpret_cast<float2*>(ob + (size_t)(row0 + 8) * rs + nt * 8 + 2 * u) =
            make_float2(o[nt][2] * i1, o[nt][3] * i1);
    }
}

}  // namespace

extern "C" void kernel_launch(void* const* d_in, const int* in_sizes, int n_in,
                              void* d_out, int out_size)
{
    (void)in_sizes; (void)n_in; (void)out_size;
    const float* q = (const float*)d_in[0];
    const float* k = (const float*)d_in[1];
    const float* v = (const float*)d_in[2];
    float* out = (float*)d_out;

    // pre-pass: 1,048,576 float4 per tensor
    dim3 pgrid(4096, 3);
    prepass_kernel<<<pgrid, 256>>>(q, k, v);

    cudaFuncSetAttribute(fa_mma_kernel,
                         cudaFuncAttributeMaxDynamicSharedMemorySize, SMEM_BYTES);
    dim3 grid(N / BQ, 2 * 16);
    fa_mma_kernel<<<grid, THREADS, SMEM_BYTES>>>(out);
}

// round 6
// speedup vs baseline: 3.9472x; 1.3159x over previous
#include <cuda_runtime.h>
#include <cuda_fp16.h>
#include <stdint.h>
#include <math.h>

// Flash attention, mma.sync fp16 2x-split + fp16 pre-pass + cp.async pipeline.
// B=2, N=2048, H=16, D=64, fp32 in/out. out = softmax(QK^T/8) V.
// GEMM1: Qh*(Kh+Kl)  (q rounding err ~3e-4 in exp2-domain scores)
// GEMM2: Ph*(Vh+Vl)  (p rounding err ~2.8e-4 rel)

#define SW128(o) ((o) ^ (((o) >> 3) & 0x70))

namespace {

constexpr int N = 2048;
constexpr int BQ = 128;
constexpr int BK = 64;
constexpr int THREADS = 256;
constexpr int NT = N / BK;  // 32

constexpr float QSCALE = 0.125f * 1.44269504088896340736f;  // 1/sqrt(64)*log2(e)

// fp16 scratch planes: [qh, kh, kl, vh, vl], each [32 bh][2048 n][64 d]
constexpr size_t PL = (size_t)32 * 2048 * 64;
__device__ __half g_scr[5 * PL];

// smem (bytes): Qh 16K, then 2 KV buffers of 32K (KH 8K, KL 8K, VH 8K, VL 8K)
constexpr uint32_t OQH = 0;
constexpr uint32_t OKV0 = 16384;
constexpr uint32_t KVSTRIDE = 32768;
constexpr uint32_t SUB_KH = 0, SUB_KL = 8192, SUB_VH = 16384, SUB_VL = 24576;
constexpr uint32_t SMEM_BYTES = 81920;  // 80KB -> 2 CTAs/SM (reg-bound anyway)

__device__ __forceinline__ uint32_t smem_u32(const void* p) {
    uint32_t a;
    asm("{ .reg .u64 t; cvta.to.shared.u64 t, %1; cvt.u32.u64 %0, t; }" : "=r"(a) : "l"(p));
    return a;
}

// pack two fp32 -> f16x2 (x0 low)
__device__ __forceinline__ uint32_t pkh(float x0, float x1) {
    uint32_t r;
    asm("cvt.rn.f16x2.f32 %0, %2, %1;" : "=r"(r) : "f"(x0), "f"(x1));
    return r;
}

// split (x0,x1) into fp16 hi pair + fp16 lo-residual pair
__device__ __forceinline__ void split2h(float x0, float x1, uint32_t& h, uint32_t& l) {
    h = pkh(x0, x1);
    __half2 hh = *reinterpret_cast<__half2*>(&h);
    float2 hf = __half22float2(hh);
    l = pkh(x0 - hf.x, x1 - hf.y);
}

__device__ __forceinline__ float ex2(float x) {
    float r; asm("ex2.approx.f32 %0, %1;" : "=f"(r) : "f"(x)); return r;
}

__device__ __forceinline__ void ldsm4(uint32_t a, uint32_t& r0, uint32_t& r1,
                                      uint32_t& r2, uint32_t& r3) {
    asm volatile("ldmatrix.sync.aligned.m8n8.x4.shared.b16 {%0,%1,%2,%3}, [%4];"
                 : "=r"(r0), "=r"(r1), "=r"(r2), "=r"(r3) : "r"(a));
}

__device__ __forceinline__ void ldsm4t(uint32_t a, uint32_t& r0, uint32_t& r1,
                                       uint32_t& r2, uint32_t& r3) {
    asm volatile("ldmatrix.sync.aligned.m8n8.x4.trans.shared.b16 {%0,%1,%2,%3}, [%4];"
                 : "=r"(r0), "=r"(r1), "=r"(r2), "=r"(r3) : "r"(a));
}

__device__ __forceinline__ void mma16816(float* c, const uint32_t* a, uint32_t b0, uint32_t b1) {
    asm volatile("mma.sync.aligned.m16n8k16.row.col.f32.f16.f16.f32 "
                 "{%0,%1,%2,%3}, {%4,%5,%6,%7}, {%8,%9}, {%0,%1,%2,%3};"
                 : "+f"(c[0]), "+f"(c[1]), "+f"(c[2]), "+f"(c[3])
                 : "r"(a[0]), "r"(a[1]), "r"(a[2]), "r"(a[3]), "r"(b0), "r"(b1));
}

__device__ __forceinline__ void cpa16(uint32_t dst, const void* src) {
    asm volatile("cp.async.ca.shared.global [%0], [%1], 16;" :: "r"(dst), "l"(src));
}
__device__ __forceinline__ void cpa_commit() {
    asm volatile("cp.async.commit_group;" ::: "memory");
}
template <int n>
__device__ __forceinline__ void cpa_wait() {
    asm volatile("cp.async.wait_group %0;" :: "n"(n) : "memory");
}

// ---------------- pre-pass: fp32 -> fp16 planes, [bh][n][64] ----------------
__global__ void prepass_kernel(const float* __restrict__ q,
                               const float* __restrict__ k,
                               const float* __restrict__ v)
{
    const int which = blockIdx.y;  // 0=q(hi only), 1=k(hi+lo), 2=v(hi+lo)
    const float* src = (which == 0) ? q : ((which == 1) ? k : v);
    const float scale = (which == 0) ? QSCALE : 1.0f;
    __half* hi = g_scr + ((which == 0) ? 0 : (which == 1) ? 1 : 3) * PL;
    __half* lo = hi + PL;  // valid for k, v

    size_t i = (size_t)blockIdx.x * blockDim.x + threadIdx.x;  // float4 index
    float4 w = reinterpret_cast<const float4*>(src)[i];
    uint32_t d4 = (uint32_t)(i & 15) << 2;
    uint32_t nh = (uint32_t)(i >> 4);
    uint32_t h = nh & 15;
    uint32_t bn = nh >> 4;
    uint32_t n = bn & 2047;
    uint32_t b = bn >> 11;
    size_t o = ((size_t)(b * 16 + h) * 2048 + n) * 64 + d4;

    uint32_t h0, l0, h1, l1;
    split2h(w.x * scale, w.y * scale, h0, l0);
    split2h(w.z * scale, w.w * scale, h1, l1);
    *reinterpret_cast<uint2*>(hi + o) = make_uint2(h0, h1);
    if (which != 0)
        *reinterpret_cast<uint2*>(lo + o) = make_uint2(l0, l1);
}

// ---------------- main kernel ----------------
__global__ __launch_bounds__(THREADS, 2)
void fa_mma_kernel(float* __restrict__ out)
{
    extern __shared__ char sm[];
    const uint32_t smb = smem_u32(sm);
    const int tid = threadIdx.x;
    const int lane = tid & 31;
    const int wid = tid >> 5;
    const int g = lane >> 2;
    const int u = lane & 3;
    const int li = lane & 7;
    const int sel = lane >> 3;

    const int q0 = blockIdx.x * BQ;
    const int bh = blockIdx.y;
    const int b = bh >> 4;
    const int h = bh & 15;

    const __half* qh_p = g_scr + 0 * PL + (size_t)bh * 2048 * 64;
    const __half* kh_p = g_scr + 1 * PL + (size_t)bh * 2048 * 64;
    const __half* kl_p = g_scr + 2 * PL + (size_t)bh * 2048 * 64;
    const __half* vh_p = g_scr + 3 * PL + (size_t)bh * 2048 * 64;
    const __half* vl_p = g_scr + 4 * PL + (size_t)bh * 2048 * 64;

    const size_t rs = 1024;
    float* ob = out + (size_t)b * N * rs + (size_t)h * 64;

    // ---- issue Q cp.asyncs (group 1) ----
    #pragma unroll
    for (int j = 0; j < 4; j++) {
        int idx = tid + j * THREADS;       // 128 rows x 8 chunks
        int row = idx >> 3, c = idx & 7;
        uint32_t off = SW128((uint32_t)(row * 128 + c * 16));
        cpa16(smb + OQH + off, qh_p + (size_t)(q0 + row) * 64 + c * 8);
    }
    cpa_commit();

    auto issue_kv = [&](int buf, int t) {
        uint32_t base = smb + OKV0 + (uint32_t)buf * KVSTRIDE;
        int k0 = t * BK;
        #pragma unroll
        for (int j = 0; j < 2; j++) {
            int idx = tid + j * THREADS;   // 64 rows x 8 chunks
            int row = idx >> 3, c = idx & 7;
            uint32_t off = SW128((uint32_t)(row * 128 + c * 16));
            size_t go = (size_t)(k0 + row) * 64 + c * 8;
            cpa16(base + SUB_KH + off, kh_p + go);
            cpa16(base + SUB_KL + off, kl_p + go);
            cpa16(base + SUB_VH + off, vh_p + go);
            cpa16(base + SUB_VL + off, vl_p + go);
        }
        cpa_commit();
    };

    issue_kv(0, 0);
    cpa_wait<1>();       // Q ready
    __syncthreads();

    // ---- Q fragments (hi only) ----
    uint32_t qh[4][4];
    {
        int qrow = wid * 16 + li + ((sel & 1) ? 8 : 0);
        #pragma unroll
        for (int ks = 0; ks < 4; ks++) {
            uint32_t off = (uint32_t)(qrow * 128 + ks * 32 + ((sel & 2) ? 16 : 0));
            ldsm4(smb + OQH + SW128(off), qh[ks][0], qh[ks][1], qh[ks][2], qh[ks][3]);
        }
    }

    float mrow0 = -INFINITY, mrow1 = -INFINITY;
    float lsum0 = 0.0f, lsum1 = 0.0f;
    float o[8][4];
    #pragma unroll
    for (int n = 0; n < 8; n++)
        #pragma unroll
        for (int j = 0; j < 4; j++) o[n][j] = 0.0f;

    for (int t = 0; t < NT; t++) {
        const int cur = t & 1;
        const int nxt = cur ^ 1;
        const bool pf = (t + 1 < NT);

        __syncthreads();
        if (pf) issue_kv(nxt, t + 1);
        if (pf) cpa_wait<1>(); else cpa_wait<0>();
        __syncthreads();

        const uint32_t kb = smb + OKV0 + (uint32_t)cur * KVSTRIDE;

        // ---- GEMM1: S(16x64) = Qh (Kh + Kl)^T ----
        float s[8][4];
        #pragma unroll
        for (int n = 0; n < 8; n++)
            #pragma unroll
            for (int j = 0; j < 4; j++) s[n][j] = 0.0f;

        #pragma unroll
        for (int nt = 0; nt < 8; nt++) {
            uint32_t bhv[4][2], blv[4][2];
            uint32_t base = (uint32_t)((nt * 8 + li) * 128 + sel * 16);
            ldsm4(kb + SUB_KH + SW128(base),      bhv[0][0], bhv[0][1], bhv[1][0], bhv[1][1]);
            ldsm4(kb + SUB_KH + SW128(base + 64), bhv[2][0], bhv[2][1], bhv[3][0], bhv[3][1]);
            ldsm4(kb + SUB_KL + SW128(base),      blv[0][0], blv[0][1], blv[1][0], blv[1][1]);
            ldsm4(kb + SUB_KL + SW128(base + 64), blv[2][0], blv[2][1], blv[3][0], blv[3][1]);
            #pragma unroll
            for (int ks = 0; ks < 4; ks++) {
                mma16816(s[nt], qh[ks], bhv[ks][0], bhv[ks][1]);
                mma16816(s[nt], qh[ks], blv[ks][0], blv[ks][1]);
            }
        }

        // ---- online softmax (exp2 domain) ----
        float tm0 = s[0][0], tm1 = s[0][2];
        #pragma unroll
        for (int nt = 0; nt < 8; nt++) {
            tm0 = fmaxf(tm0, fmaxf(s[nt][0], s[nt][1]));
            tm1 = fmaxf(tm1, fmaxf(s[nt][2], s[nt][3]));
        }
        tm0 = fmaxf(tm0, __shfl_xor_sync(0xffffffffu, tm0, 1));
        tm0 = fmaxf(tm0, __shfl_xor_sync(0xffffffffu, tm0, 2));
        tm1 = fmaxf(tm1, __shfl_xor_sync(0xffffffffu, tm1, 1));
        tm1 = fmaxf(tm1, __shfl_xor_sync(0xffffffffu, tm1, 2));

        float mn0 = fmaxf(mrow0, tm0), mn1 = fmaxf(mrow1, tm1);
        float a0 = ex2(mrow0 - mn0), a1 = ex2(mrow1 - mn1);
        mrow0 = mn0; mrow1 = mn1;
        lsum0 *= a0; lsum1 *= a1;

        #pragma unroll
        for (int nt = 0; nt < 8; nt++) {
            s[nt][0] = ex2(s[nt][0] - mn0);
            s[nt][1] = ex2(s[nt][1] - mn0);
            s[nt][2] = ex2(s[nt][2] - mn1);
            s[nt][3] = ex2(s[nt][3] - mn1);
            lsum0 += s[nt][0] + s[nt][1];
            lsum1 += s[nt][2] + s[nt][3];
        }
        #pragma unroll
        for (int n = 0; n < 8; n++) {
            o[n][0] *= a0; o[n][1] *= a0;
            o[n][2] *= a1; o[n][3] *= a1;
        }

        // ---- GEMM2: O(16x64) += Ph (Vh + Vl) ----
        #pragma unroll
        for (int ks = 0; ks < 4; ks++) {
            uint32_t ah[4];
            ah[0] = pkh(s[2 * ks][0],     s[2 * ks][1]);
            ah[1] = pkh(s[2 * ks][2],     s[2 * ks][3]);
            ah[2] = pkh(s[2 * ks + 1][0], s[2 * ks + 1][1]);
            ah[3] = pkh(s[2 * ks + 1][2], s[2 * ks + 1][3]);
            uint32_t vbase = (uint32_t)((ks * 16 + li + ((sel & 1) ? 8 : 0)) * 128
                                        + ((sel & 2) ? 16 : 0));
            #pragma unroll
            for (int pr = 0; pr < 4; pr++) {
                uint32_t r0, r1, r2, r3, t0, t1, t2, t3;
                uint32_t off = vbase + pr * 32;
                ldsm4t(kb + SUB_VH + SW128(off), r0, r1, r2, r3);
                ldsm4t(kb + SUB_VL + SW128(off), t0, t1, t2, t3);
                mma16816(o[2 * pr],     ah, r0, r1);
                mma16816(o[2 * pr],     ah, t0, t1);
                mma16816(o[2 * pr + 1], ah, r2, r3);
                mma16816(o[2 * pr + 1], ah, t2, t3);
            }
        }
    }

    // ---- epilogue ----
    lsum0 += __shfl_xor_sync(0xffffffffu, lsum0, 1);
    lsum0 += __shfl_xor_sync(0xffffffffu, lsum0, 2);
    lsum1 += __shfl_xor_sync(0xffffffffu, lsum1, 1);
    lsum1 += __shfl_xor_sync(0xffffffffu, lsum1, 2);
    float i0 = 1.0f / lsum0, i1 = 1.0f / lsum1;

    const int row0 = q0 + wid * 16 + g;
    #pragma unroll
    for (int nt = 0; nt < 8; nt++) {
        *reinterpret_cast<float2*>(ob + (size_t)row0 * rs + nt * 8 + 2 * u) =
            make_float2(o[nt][0] * i0, o[nt][1] * i0);
        *reinterpret_cast<float2*>(ob + (size_t)(row0 + 8) * rs + nt * 8 + 2 * u) =
            make_float2(o[nt][2] * i1, o[nt][3] * i1);
    }
}

}  // namespace

extern "C" void kernel_launch(void* const* d_in, const int* in_sizes, int n_in,
                              void* d_out, int out_size)
{
    (void)in_sizes; (void)n_in; (void)out_size;
    const float* q = (const float*)d_in[0];
    const float* k = (const float*)d_in[1];
    const float* v = (const float*)d_in[2];
    float* out = (float*)d_out;

    dim3 pgrid(4096, 3);
    prepass_kernel<<<pgrid, 256>>>(q, k, v);

    cudaFuncSetAttribute(fa_mma_kernel,
                         cudaFuncAttributeMaxDynamicSharedMemorySize, SMEM_BYTES);
    dim3 grid(N / BQ, 2 * 16);
    fa_mma_kernel<<<grid, THREADS, SMEM_BYTES>>>(out);
}

// round 7
// speedup vs baseline: 6.6718x; 1.6903x over previous
#include <cuda_runtime.h>
#include <cuda_fp16.h>
#include <stdint.h>
#include <math.h>

// Flash attention, pure-fp16 mma.sync + fp16 pre-pass + cp.async pipeline.
// B=2, N=2048, H=16, D=64, fp32 in/out. out = softmax(QK^T/8) V.
// All operands single fp16 (no residual terms); fp32 accumulate.
// Error budget ~3.5e-4 rel (threshold 1e-3).

#define SW128(o) ((o) ^ (((o) >> 3) & 0x70))

namespace {

constexpr int N = 2048;
constexpr int BQ = 128;
constexpr int BK = 64;
constexpr int THREADS = 256;
constexpr int NT = N / BK;  // 32

constexpr float QSCALE = 0.125f * 1.44269504088896340736f;  // 1/sqrt(64)*log2(e)

// fp16 scratch planes: [qh, kh, vh], each [32 bh][2048 n][64 d]
constexpr size_t PL = (size_t)32 * 2048 * 64;
__device__ __half g_scr[3 * PL];

// smem (bytes): Qh 16K, then 2 KV buffers of 16K (KH 8K, VH 8K)
constexpr uint32_t OQH = 0;
constexpr uint32_t OKV0 = 16384;
constexpr uint32_t KVSTRIDE = 16384;
constexpr uint32_t SUB_KH = 0, SUB_VH = 8192;
constexpr uint32_t SMEM_BYTES = 49152;

__device__ __forceinline__ uint32_t smem_u32(const void* p) {
    uint32_t a;
    asm("{ .reg .u64 t; cvta.to.shared.u64 t, %1; cvt.u32.u64 %0, t; }" : "=r"(a) : "l"(p));
    return a;
}

// pack two fp32 -> f16x2 (x0 low)
__device__ __forceinline__ uint32_t pkh(float x0, float x1) {
    uint32_t r;
    asm("cvt.rn.f16x2.f32 %0, %2, %1;" : "=r"(r) : "f"(x0), "f"(x1));
    return r;
}

__device__ __forceinline__ float ex2(float x) {
    float r; asm("ex2.approx.f32 %0, %1;" : "=f"(r) : "f"(x)); return r;
}

__device__ __forceinline__ void ldsm4(uint32_t a, uint32_t& r0, uint32_t& r1,
                                      uint32_t& r2, uint32_t& r3) {
    asm volatile("ldmatrix.sync.aligned.m8n8.x4.shared.b16 {%0,%1,%2,%3}, [%4];"
                 : "=r"(r0), "=r"(r1), "=r"(r2), "=r"(r3) : "r"(a));
}

__device__ __forceinline__ void ldsm4t(uint32_t a, uint32_t& r0, uint32_t& r1,
                                       uint32_t& r2, uint32_t& r3) {
    asm volatile("ldmatrix.sync.aligned.m8n8.x4.trans.shared.b16 {%0,%1,%2,%3}, [%4];"
                 : "=r"(r0), "=r"(r1), "=r"(r2), "=r"(r3) : "r"(a));
}

__device__ __forceinline__ void mma16816(float* c, const uint32_t* a, uint32_t b0, uint32_t b1) {
    asm volatile("mma.sync.aligned.m16n8k16.row.col.f32.f16.f16.f32 "
                 "{%0,%1,%2,%3}, {%4,%5,%6,%7}, {%8,%9}, {%0,%1,%2,%3};"
                 : "+f"(c[0]), "+f"(c[1]), "+f"(c[2]), "+f"(c[3])
                 : "r"(a[0]), "r"(a[1]), "r"(a[2]), "r"(a[3]), "r"(b0), "r"(b1));
}

__device__ __forceinline__ void cpa16(uint32_t dst, const void* src) {
    asm volatile("cp.async.ca.shared.global [%0], [%1], 16;" :: "r"(dst), "l"(src));
}
__device__ __forceinline__ void cpa_commit() {
    asm volatile("cp.async.commit_group;" ::: "memory");
}
template <int n>
__device__ __forceinline__ void cpa_wait() {
    asm volatile("cp.async.wait_group %0;" :: "n"(n) : "memory");
}

// ---------------- pre-pass: fp32 -> fp16 planes, [bh][n][64] ----------------
__global__ void prepass_kernel(const float* __restrict__ q,
                               const float* __restrict__ k,
                               const float* __restrict__ v)
{
    const int which = blockIdx.y;  // 0=q, 1=k, 2=v
    const float* src = (which == 0) ? q : ((which == 1) ? k : v);
    const float scale = (which == 0) ? QSCALE : 1.0f;
    __half* dst = g_scr + (size_t)which * PL;

    size_t i = (size_t)blockIdx.x * blockDim.x + threadIdx.x;  // float4 index
    float4 w = reinterpret_cast<const float4*>(src)[i];
    uint32_t d4 = (uint32_t)(i & 15) << 2;
    uint32_t nh = (uint32_t)(i >> 4);
    uint32_t h = nh & 15;
    uint32_t bn = nh >> 4;
    uint32_t n = bn & 2047;
    uint32_t b = bn >> 11;
    size_t o = ((size_t)(b * 16 + h) * 2048 + n) * 64 + d4;

    *reinterpret_cast<uint2*>(dst + o) =
        make_uint2(pkh(w.x * scale, w.y * scale), pkh(w.z * scale, w.w * scale));
}

// ---------------- main kernel ----------------
__global__ __launch_bounds__(THREADS, 2)
void fa_mma_kernel(float* __restrict__ out)
{
    extern __shared__ char sm[];
    const uint32_t smb = smem_u32(sm);
    const int tid = threadIdx.x;
    const int lane = tid & 31;
    const int wid = tid >> 5;
    const int g = lane >> 2;
    const int u = lane & 3;
    const int li = lane & 7;
    const int sel = lane >> 3;

    const int q0 = blockIdx.x * BQ;
    const int bh = blockIdx.y;
    const int b = bh >> 4;
    const int h = bh & 15;

    const __half* qh_p = g_scr + 0 * PL + (size_t)bh * 2048 * 64;
    const __half* kh_p = g_scr + 1 * PL + (size_t)bh * 2048 * 64;
    const __half* vh_p = g_scr + 2 * PL + (size_t)bh * 2048 * 64;

    const size_t rs = 1024;
    float* ob = out + (size_t)b * N * rs + (size_t)h * 64;

    // ---- issue Q cp.asyncs (group 1) ----
    #pragma unroll
    for (int j = 0; j < 4; j++) {
        int idx = tid + j * THREADS;       // 128 rows x 8 chunks
        int row = idx >> 3, c = idx & 7;
        uint32_t off = SW128((uint32_t)(row * 128 + c * 16));
        cpa16(smb + OQH + off, qh_p + (size_t)(q0 + row) * 64 + c * 8);
    }
    cpa_commit();

    auto issue_kv = [&](int buf, int t) {
        uint32_t base = smb + OKV0 + (uint32_t)buf * KVSTRIDE;
        int k0 = t * BK;
        #pragma unroll
        for (int j = 0; j < 2; j++) {
            int idx = tid + j * THREADS;   // 64 rows x 8 chunks
            int row = idx >> 3, c = idx & 7;
            uint32_t off = SW128((uint32_t)(row * 128 + c * 16));
            size_t go = (size_t)(k0 + row) * 64 + c * 8;
            cpa16(base + SUB_KH + off, kh_p + go);
            cpa16(base + SUB_VH + off, vh_p + go);
        }
        cpa_commit();
    };

    issue_kv(0, 0);
    cpa_wait<1>();       // Q ready
    __syncthreads();

    // ---- Q fragments ----
    uint32_t qh[4][4];
    {
        int qrow = wid * 16 + li + ((sel & 1) ? 8 : 0);
        #pragma unroll
        for (int ks = 0; ks < 4; ks++) {
            uint32_t off = (uint32_t)(qrow * 128 + ks * 32 + ((sel & 2) ? 16 : 0));
            ldsm4(smb + OQH + SW128(off), qh[ks][0], qh[ks][1], qh[ks][2], qh[ks][3]);
        }
    }

    float mrow0 = -INFINITY, mrow1 = -INFINITY;
    float lsum0 = 0.0f, lsum1 = 0.0f;
    float o[8][4];
    #pragma unroll
    for (int n = 0; n < 8; n++)
        #pragma unroll
        for (int j = 0; j < 4; j++) o[n][j] = 0.0f;

    for (int t = 0; t < NT; t++) {
        const int cur = t & 1;
        const int nxt = cur ^ 1;
        const bool pf = (t + 1 < NT);

        __syncthreads();
        if (pf) issue_kv(nxt, t + 1);
        if (pf) cpa_wait<1>(); else cpa_wait<0>();
        __syncthreads();

        const uint32_t kb = smb + OKV0 + (uint32_t)cur * KVSTRIDE;

        // ---- GEMM1: S(16x64) = Qh Kh^T ----
        float s[8][4];
        #pragma unroll
        for (int n = 0; n < 8; n++)
            #pragma unroll
            for (int j = 0; j < 4; j++) s[n][j] = 0.0f;

        #pragma unroll
        for (int nt = 0; nt < 8; nt++) {
            uint32_t bhv[4][2];
            uint32_t base = (uint32_t)((nt * 8 + li) * 128 + sel * 16);
            ldsm4(kb + SUB_KH + SW128(base),      bhv[0][0], bhv[0][1], bhv[1][0], bhv[1][1]);
            ldsm4(kb + SUB_KH + SW128(base + 64), bhv[2][0], bhv[2][1], bhv[3][0], bhv[3][1]);
            #pragma unroll
            for (int ks = 0; ks < 4; ks++)
                mma16816(s[nt], qh[ks], bhv[ks][0], bhv[ks][1]);
        }

        // ---- online softmax (exp2 domain) ----
        float tm0 = s[0][0], tm1 = s[0][2];
        #pragma unroll
        for (int nt = 0; nt < 8; nt++) {
            tm0 = fmaxf(tm0, fmaxf(s[nt][0], s[nt][1]));
            tm1 = fmaxf(tm1, fmaxf(s[nt][2], s[nt][3]));
        }
        tm0 = fmaxf(tm0, __shfl_xor_sync(0xffffffffu, tm0, 1));
        tm0 = fmaxf(tm0, __shfl_xor_sync(0xffffffffu, tm0, 2));
        tm1 = fmaxf(tm1, __shfl_xor_sync(0xffffffffu, tm1, 1));
        tm1 = fmaxf(tm1, __shfl_xor_sync(0xffffffffu, tm1, 2));

        float mn0 = fmaxf(mrow0, tm0), mn1 = fmaxf(mrow1, tm1);
        float a0 = ex2(mrow0 - mn0), a1 = ex2(mrow1 - mn1);
        mrow0 = mn0; mrow1 = mn1;
        lsum0 *= a0; lsum1 *= a1;

        #pragma unroll
        for (int nt = 0; nt < 8; nt++) {
            s[nt][0] = ex2(s[nt][0] - mn0);
            s[nt][1] = ex2(s[nt][1] - mn0);
            s[nt][2] = ex2(s[nt][2] - mn1);
            s[nt][3] = ex2(s[nt][3] - mn1);
            lsum0 += s[nt][0] + s[nt][1];
            lsum1 += s[nt][2] + s[nt][3];
        }
        #pragma unroll
        for (int n = 0; n < 8; n++) {
            o[n][0] *= a0; o[n][1] *= a0;
            o[n][2] *= a1; o[n][3] *= a1;
        }

        // ---- GEMM2: O(16x64) += Ph Vh ----
        #pragma unroll
        for (int ks = 0; ks < 4; ks++) {
            uint32_t ah[4];
            ah[0] = pkh(s[2 * ks][0],     s[2 * ks][1]);
            ah[1] = pkh(s[2 * ks][2],     s[2 * ks][3]);
            ah[2] = pkh(s[2 * ks + 1][0], s[2 * ks + 1][1]);
            ah[3] = pkh(s[2 * ks + 1][2], s[2 * ks + 1][3]);
            uint32_t vbase = (uint32_t)((ks * 16 + li + ((sel & 1) ? 8 : 0)) * 128
                                        + ((sel & 2) ? 16 : 0));
            #pragma unroll
            for (int pr = 0; pr < 4; pr++) {
                uint32_t r0, r1, r2, r3;
                ldsm4t(kb + SUB_VH + SW128(vbase + pr * 32), r0, r1, r2, r3);
                mma16816(o[2 * pr],     ah, r0, r1);
                mma16816(o[2 * pr + 1], ah, r2, r3);
            }
        }
    }

    // ---- epilogue ----
    lsum0 += __shfl_xor_sync(0xffffffffu, lsum0, 1);
    lsum0 += __shfl_xor_sync(0xffffffffu, lsum0, 2);
    lsum1 += __shfl_xor_sync(0xffffffffu, lsum1, 1);
    lsum1 += __shfl_xor_sync(0xffffffffu, lsum1, 2);
    float i0 = 1.0f / lsum0, i1 = 1.0f / lsum1;

    const int row0 = q0 + wid * 16 + g;
    #pragma unroll
    for (int nt = 0; nt < 8; nt++) {
        *reinterpret_cast<float2*>(ob + (size_t)row0 * rs + nt * 8 + 2 * u) =
            make_float2(o[nt][0] * i0, o[nt][1] * i0);
        *reinterpret_cast<float2*>(ob + (size_t)(row0 + 8) * rs + nt * 8 + 2 * u) =
            make_float2(o[nt][2] * i1, o[nt][3] * i1);
    }
}

}  // namespace

extern "C" void kernel_launch(void* const* d_in, const int* in_sizes, int n_in,
                              void* d_out, int out_size)
{
    (void)in_sizes; (void)n_in; (void)out_size;
    const float* q = (const float*)d_in[0];
    const float* k = (const float*)d_in[1];
    const float* v = (const float*)d_in[2];
    float* out = (float*)d_out;

    dim3 pgrid(4096, 3);
    prepass_kernel<<<pgrid, 256>>>(q, k, v);

    cudaFuncSetAttribute(fa_mma_kernel,
                         cudaFuncAttributeMaxDynamicSharedMemorySize, SMEM_BYTES);
    dim3 grid(N / BQ, 2 * 16);
    fa_mma_kernel<<<grid, THREADS, SMEM_BYTES>>>(out);
}